// round 15
// baseline (speedup 1.0000x reference)
#include <cuda_runtime.h>
#include <cuda_fp16.h>
#include <cstdint>

#define B_ 8
#define S_ 2048
#define H_ 1024
#define M_ (B_ * S_)   // 16384

// Scratch (static __device__ — allocation-free per harness rules)
static __device__ __half g_Q [(size_t)B_ * S_ * H_];   // 32 MB fp16
static __device__ __half g_K [(size_t)B_ * S_ * H_];   // 32 MB fp16
static __device__ __half g_V [(size_t)B_ * S_ * H_];   // 32 MB fp16
static __device__ __half g_Ph[(size_t)B_ * S_ * S_];   // 64 MB logits -> probs fp16
static __device__ float  g_d1[(size_t)B_ * S_];
static __device__ __half g_HS[(size_t)B_ * S_ * H_];   // 32 MB fp16 hidden_states
static __device__ __half g_W [(size_t)3 * H_ * H_];    // 6 MB fp16 Wq|Wk|Wv

// ---------------------------------------------------------------------------
// helpers
// ---------------------------------------------------------------------------
__device__ __forceinline__ void mma_f16(float c[4], const uint32_t a[4], const uint32_t b[2]) {
    asm volatile(
        "mma.sync.aligned.m16n8k16.row.col.f32.f16.f16.f32 "
        "{%0,%1,%2,%3}, {%4,%5,%6,%7}, {%8,%9}, {%0,%1,%2,%3};"
        : "+f"(c[0]), "+f"(c[1]), "+f"(c[2]), "+f"(c[3])
        : "r"(a[0]), "r"(a[1]), "r"(a[2]), "r"(a[3]), "r"(b[0]), "r"(b[1]));
}
__device__ __forceinline__ void ldsm_x4(uint32_t r[4], uint32_t addr) {
    asm volatile("ldmatrix.sync.aligned.m8n8.x4.shared.b16 {%0,%1,%2,%3}, [%4];"
        : "=r"(r[0]), "=r"(r[1]), "=r"(r[2]), "=r"(r[3]) : "r"(addr));
}
__device__ __forceinline__ void ldsm_x4_t(uint32_t r[4], uint32_t addr) {
    asm volatile("ldmatrix.sync.aligned.m8n8.x4.trans.shared.b16 {%0,%1,%2,%3}, [%4];"
        : "=r"(r[0]), "=r"(r[1]), "=r"(r[2]), "=r"(r[3]) : "r"(addr));
}
__device__ __forceinline__ void cp_async16(uint32_t smem_dst, const void* gsrc) {
    asm volatile("cp.async.cg.shared.global [%0], [%1], 16;\n" :: "r"(smem_dst), "l"(gsrc));
}
__device__ __forceinline__ void cp_commit() {
    asm volatile("cp.async.commit_group;\n" ::: "memory");
}
__device__ __forceinline__ void cp_wait2() {
    asm volatile("cp.async.wait_group 2;\n" ::: "memory");
}
__device__ __forceinline__ uint32_t pack_h2(float a, float b) {
    __half2 h = __float22half2_rn(make_float2(a, b));
    return *(uint32_t*)&h;
}

// ---------------------------------------------------------------------------
// fp32 -> fp16 pre-round (8 elems/thread).  z-indexed multi-tensor variant.
// ---------------------------------------------------------------------------
__global__ __launch_bounds__(256) void round_f16_kernel(
    const float* __restrict__ src, __half* __restrict__ dst)
{
    size_t i = ((size_t)blockIdx.x * 256 + threadIdx.x) * 8;
    float4 a = *(const float4*)(src + i);
    float4 b = *(const float4*)(src + i + 4);
    uint4 u;
    u.x = pack_h2(a.x, a.y); u.y = pack_h2(a.z, a.w);
    u.z = pack_h2(b.x, b.y); u.w = pack_h2(b.z, b.w);
    *(uint4*)(dst + i) = u;
}
__global__ __launch_bounds__(256) void round_w_kernel(
    const float* __restrict__ Wq, const float* __restrict__ Wk,
    const float* __restrict__ Wv)
{
    const float* src = (blockIdx.z == 0) ? Wq : (blockIdx.z == 1) ? Wk : Wv;
    __half* dst = g_W + (size_t)blockIdx.z * H_ * H_;
    size_t i = ((size_t)blockIdx.x * 256 + threadIdx.x) * 8;
    float4 a = *(const float4*)(src + i);
    float4 b = *(const float4*)(src + i + 4);
    uint4 u;
    u.x = pack_h2(a.x, a.y); u.y = pack_h2(a.z, a.w);
    u.z = pack_h2(b.x, b.y); u.w = pack_h2(b.z, b.w);
    *(uint4*)(dst + i) = u;
}

// ---------------------------------------------------------------------------
// Pipelined fp16 GEMM mainloop: CTA tile 128x256, warp tile 64x64, KC=64,
// 3-stage cp.async.  mma m16n8k16 + ldmatrix.
//   BMODE 0: Bsrc [N,K] row-major, staged Bs[n][k] pitch 72
//   BMODE 1: Bsrc [K,N] row-major, staged Bs[k][n] pitch 264, ldmatrix.trans
// 256 threads = 8 warps (2 row x 4 col).
// ---------------------------------------------------------------------------
#define APITCH 72
#define ASZ (128 * APITCH)            // 9216 halves per A stage
#define BSZ0 (256 * 72)               // 18432 halves per B stage (BMODE0)
#define BPITCH1 264
#define BSZ1 (64 * BPITCH1)           // 16896 halves per B stage (BMODE1)

template<int BMODE>
__device__ __forceinline__ void gemm_pipe(
    const __half* __restrict__ A, int lda,
    const __half* __restrict__ Bsrc, int ldb,
    int m0, int n0, int K,
    __half* As, __half* Bs,
    float acc[4][8][4])
{
    const int BSZ = (BMODE == 0) ? BSZ0 : BSZ1;
    const uint32_t As_s = (uint32_t)__cvta_generic_to_shared(As);
    const uint32_t Bs_s = (uint32_t)__cvta_generic_to_shared(Bs);

    const int tid  = threadIdx.x;
    const int lane = tid & 31;
    const int w    = tid >> 5;
    const int wm   = (w >> 2) * 64;   // warp row origin (0/64)
    const int wn   = (w & 3)  * 64;   // warp col origin (0..192)

    // ldmatrix lane coords
    const int lrow = lane & 15;
    const int lc8  = (lane >> 4) * 8;
    const int tkoff = ((lane >> 3) & 1) * 8 + (lane & 7);  // trans: k row
    const int tnoff = (lane >> 4) * 8;                     // trans: n col

    // staging coords
    const int ar = tid >> 3, ac = (tid & 7) * 8;     // A / B0: 8x16B per row
    const int br1 = tid >> 5, bc1 = (tid & 31) * 8;  // B1: 32x16B per row

    auto stage = [&](int buf, int cidx) {
        int k0 = cidx * 64;
        #pragma unroll
        for (int p = 0; p < 4; p++) {                        // A: 128 x 64h
            int r = ar + p * 32;
            cp_async16(As_s + (uint32_t)(buf * ASZ + r * APITCH + ac) * 2,
                       A + (size_t)(m0 + r) * lda + k0 + ac);
        }
        if (BMODE == 0) {
            #pragma unroll
            for (int p = 0; p < 8; p++) {                    // B: 256 x 64h
                int r = ar + p * 32;
                cp_async16(Bs_s + (uint32_t)(buf * BSZ0 + r * 72 + ac) * 2,
                           Bsrc + (size_t)(n0 + r) * ldb + k0 + ac);
            }
        } else {
            #pragma unroll
            for (int p = 0; p < 8; p++) {                    // B: 64 x 256h
                int r = br1 + p * 8;
                cp_async16(Bs_s + (uint32_t)(buf * BSZ1 + r * BPITCH1 + bc1) * 2,
                           Bsrc + (size_t)(k0 + r) * ldb + n0 + bc1);
            }
        }
    };

    const int NC = K / 64;
    stage(0, 0); cp_commit();
    stage(1, 1); cp_commit();

    for (int c = 0; c < NC; c++) {
        int buf = c % 3;
        if (c + 2 < NC) stage((c + 2) % 3, c + 2);
        cp_commit();                        // uniform group count (may be empty)
        cp_wait2();                         // group c complete
        __syncthreads();

        const uint32_t Ab = As_s + (uint32_t)(buf * ASZ) * 2;
        const uint32_t Bb = Bs_s + (uint32_t)(buf * BSZ) * 2;

        #pragma unroll
        for (int ks = 0; ks < 4; ks++) {                     // 4 x k16
            uint32_t af[4][4], bf[8][2];
            #pragma unroll
            for (int mi = 0; mi < 4; mi++)
                ldsm_x4(af[mi], Ab + (uint32_t)((wm + 16 * mi + lrow) * APITCH
                                                + ks * 16 + lc8) * 2);
            #pragma unroll
            for (int p = 0; p < 4; p++) {
                uint32_t t4[4];
                if (BMODE == 0) {
                    ldsm_x4(t4, Bb + (uint32_t)((wn + 16 * p + lrow) * 72
                                                + ks * 16 + lc8) * 2);
                    bf[2 * p][0]     = t4[0];
                    bf[2 * p + 1][0] = t4[1];
                    bf[2 * p][1]     = t4[2];
                    bf[2 * p + 1][1] = t4[3];
                } else {
                    ldsm_x4_t(t4, Bb + (uint32_t)((ks * 16 + tkoff) * BPITCH1
                                                  + wn + 16 * p + tnoff) * 2);
                    bf[2 * p][0]     = t4[0];
                    bf[2 * p][1]     = t4[1];
                    bf[2 * p + 1][0] = t4[2];
                    bf[2 * p + 1][1] = t4[3];
                }
            }
            #pragma unroll
            for (int mi = 0; mi < 4; mi++)
                #pragma unroll
                for (int ni = 0; ni < 8; ni++)
                    mma_f16(acc[mi][ni], af[mi], bf[ni]);
        }
        __syncthreads();
    }
}

// Shared-memory footprints (bytes), 3 stages
#define SMEM_TN  (3 * (ASZ + BSZ0) * 2)   // 165888 B (qkv, scores)
#define SMEM_NN  (3 * (ASZ + BSZ1) * 2)   // 156672 B (ctx)

// ---------------------------------------------------------------------------
// Kernel 1: QKV projections.  C[M,N] = HS @ W^T + bias -> fp16
// grid = (H/256, M/128, 3)
// ---------------------------------------------------------------------------
__global__ __launch_bounds__(256) void qkv_gemm(
    const float* __restrict__ bq, const float* __restrict__ bk,
    const float* __restrict__ bv)
{
    extern __shared__ __align__(16) __half smem[];
    __half* As = smem;
    __half* Bs = smem + 3 * ASZ;

    int z = blockIdx.z;
    const __half* W = g_W + (size_t)z * H_ * H_;
    const float* bias = (z == 0) ? bq : (z == 1) ? bk : bv;
    __half* out = (z == 0) ? g_Q : (z == 1) ? g_K : g_V;

    int m0 = blockIdx.y * 128, n0 = blockIdx.x * 256;
    float acc[4][8][4] = {};

    gemm_pipe<0>(g_HS, H_, W, H_, m0, n0, H_, As, Bs, acc);

    int lane = threadIdx.x & 31, w = threadIdx.x >> 5;
    int g = lane >> 2, t = lane & 3;
    int wm = (w >> 2) * 64, wn = (w & 3) * 64;

    #pragma unroll
    for (int mi = 0; mi < 4; mi++) {
        int row = m0 + wm + 16 * mi + g;
        #pragma unroll
        for (int ni = 0; ni < 8; ni++) {
            int col = n0 + wn + 8 * ni + 2 * t;
            float b0 = bias[col], b1 = bias[col + 1];
            *(uint32_t*)(out + (size_t)row * H_ + col) =
                pack_h2(acc[mi][ni][0] + b0, acc[mi][ni][1] + b1);
            *(uint32_t*)(out + (size_t)(row + 8) * H_ + col) =
                pack_h2(acc[mi][ni][2] + b0, acc[mi][ni][3] + b1);
        }
    }
}

// ---------------------------------------------------------------------------
// Kernel 2: d1[b,q] = Q[b,q,:] . dist_emb[1,:]   (one warp per row)
// ---------------------------------------------------------------------------
__global__ __launch_bounds__(256) void d1_kernel(const float* __restrict__ dist)
{
    int row  = blockIdx.x * 8 + (threadIdx.x >> 5);
    int lane = threadIdx.x & 31;
    const __half2* q2 = (const __half2*)(g_Q + (size_t)row * H_);
    const float2*  e2 = (const float2*)(dist + H_);
    float s = 0.f;
    #pragma unroll 4
    for (int i = lane; i < H_ / 2; i += 32) {
        float2 q = __half22float2(q2[i]);
        float2 e = e2[i];
        s += q.x * e.x + q.y * e.y;
    }
    #pragma unroll
    for (int o = 16; o; o >>= 1) s += __shfl_xor_sync(0xffffffffu, s, o);
    if (lane == 0) g_d1[row] = s;
}

// ---------------------------------------------------------------------------
// Kernel 3: scores per batch -> fp16 logits in g_Ph.
// logit = (Q.K^T + d1*[rel==1]) / 32 + mask.  grid = (8, 16, B)
// ---------------------------------------------------------------------------
__global__ __launch_bounds__(256) void scores_gemm(
    const int* __restrict__ rel, const float* __restrict__ mask)
{
    extern __shared__ __align__(16) __half smem[];
    __half* As = smem;
    __half* Bs = smem + 3 * ASZ;

    int b = blockIdx.z;
    const __half* A  = g_Q + (size_t)b * S_ * H_;
    const __half* Bt = g_K + (size_t)b * S_ * H_;
    __half* out        = g_Ph + (size_t)b * S_ * S_;
    const int* relb    = rel + (size_t)b * S_ * S_;
    const float* maskb = mask + (size_t)b * S_;

    int m0 = blockIdx.y * 128, n0 = blockIdx.x * 256;
    float acc[4][8][4] = {};

    gemm_pipe<0>(A, H_, Bt, H_, m0, n0, H_, As, Bs, acc);

    const float inv = 0.03125f;   // 1/sqrt(1024)
    int lane = threadIdx.x & 31, w = threadIdx.x >> 5;
    int g = lane >> 2, t = lane & 3;
    int wm = (w >> 2) * 64, wn = (w & 3) * 64;

    #pragma unroll
    for (int mi = 0; mi < 4; mi++) {
        int row = m0 + wm + 16 * mi + g;
        float dlo = g_d1[(size_t)b * S_ + row];
        float dhi = g_d1[(size_t)b * S_ + row + 8];
        #pragma unroll
        for (int ni = 0; ni < 8; ni++) {
            int col = n0 + wn + 8 * ni + 2 * t;
            float mk0 = maskb[col], mk1 = maskb[col + 1];
            int2 rlo = *(const int2*)(relb + (size_t)row * S_ + col);
            int2 rhi = *(const int2*)(relb + (size_t)(row + 8) * S_ + col);
            float o0 = (acc[mi][ni][0] + (rlo.x == 1 ? dlo : 0.f)) * inv + mk0;
            float o1 = (acc[mi][ni][1] + (rlo.y == 1 ? dlo : 0.f)) * inv + mk1;
            float o2 = (acc[mi][ni][2] + (rhi.x == 1 ? dhi : 0.f)) * inv + mk0;
            float o3 = (acc[mi][ni][3] + (rhi.y == 1 ? dhi : 0.f)) * inv + mk1;
            *(uint32_t*)(out + (size_t)row * S_ + col)       = pack_h2(o0, o1);
            *(uint32_t*)(out + (size_t)(row + 8) * S_ + col) = pack_h2(o2, o3);
        }
    }
}

// ---------------------------------------------------------------------------
// Kernel 4: row softmax over k (2048), in place fp16 on g_Ph.
// ---------------------------------------------------------------------------
__global__ __launch_bounds__(256) void softmax_k()
{
    __shared__ float red[32];
    int row = blockIdx.x;
    __half* p = g_Ph + (size_t)row * S_;
    int base = threadIdx.x * 8;

    uint4 u = *(const uint4*)(p + base);
    float x[8];
    {
        float2 a0 = __half22float2(*(__half2*)&u.x);
        float2 a1 = __half22float2(*(__half2*)&u.y);
        float2 a2 = __half22float2(*(__half2*)&u.z);
        float2 a3 = __half22float2(*(__half2*)&u.w);
        x[0]=a0.x; x[1]=a0.y; x[2]=a1.x; x[3]=a1.y;
        x[4]=a2.x; x[5]=a2.y; x[6]=a3.x; x[7]=a3.y;
    }

    float mx = x[0];
    #pragma unroll
    for (int i = 1; i < 8; i++) mx = fmaxf(mx, x[i]);
    #pragma unroll
    for (int o = 16; o; o >>= 1) mx = fmaxf(mx, __shfl_xor_sync(0xffffffffu, mx, o));
    int lane = threadIdx.x & 31, wid = threadIdx.x >> 5;
    if (lane == 0) red[wid] = mx;
    __syncthreads();
    if (wid == 0) {
        float m = (lane < 8) ? red[lane] : -1e30f;
        #pragma unroll
        for (int o = 4; o; o >>= 1) m = fmaxf(m, __shfl_xor_sync(0xffffffffu, m, o));
        if (lane == 0) red[0] = m;
    }
    __syncthreads();
    float m = red[0];

    float s = 0.f;
    #pragma unroll
    for (int i = 0; i < 8; i++) { x[i] = __expf(x[i] - m); s += x[i]; }
    #pragma unroll
    for (int o = 16; o; o >>= 1) s += __shfl_xor_sync(0xffffffffu, s, o);
    __syncthreads();
    if (lane == 0) red[wid] = s;
    __syncthreads();
    if (wid == 0) {
        float tt = (lane < 8) ? red[lane] : 0.f;
        #pragma unroll
        for (int o = 4; o; o >>= 1) tt += __shfl_xor_sync(0xffffffffu, tt, o);
        if (lane == 0) red[0] = tt;
    }
    __syncthreads();
    float invs = 1.0f / red[0];

    uint4 o;
    o.x = pack_h2(x[0] * invs, x[1] * invs);
    o.y = pack_h2(x[2] * invs, x[3] * invs);
    o.z = pack_h2(x[4] * invs, x[5] * invs);
    o.w = pack_h2(x[6] * invs, x[7] * invs);
    *(uint4*)(p + base) = o;
}

// ---------------------------------------------------------------------------
// Kernel 5: ctx per batch.  O = Ph @ V  (NN).  grid = (4, 16, B) -> fp32 d_out
// ---------------------------------------------------------------------------
__global__ __launch_bounds__(256) void ctx_gemm(float* __restrict__ outp)
{
    extern __shared__ __align__(16) __half smem[];
    __half* As = smem;
    __half* Bs = smem + 3 * ASZ;

    int b = blockIdx.z;
    const __half* A  = g_Ph + (size_t)b * S_ * S_;
    const __half* Bm = g_V  + (size_t)b * S_ * H_;
    float* out = outp + (size_t)b * S_ * H_;

    int m0 = blockIdx.y * 128, n0 = blockIdx.x * 256;
    float acc[4][8][4] = {};

    gemm_pipe<1>(A, S_, Bm, H_, m0, n0, S_, As, Bs, acc);

    int lane = threadIdx.x & 31, w = threadIdx.x >> 5;
    int g = lane >> 2, t = lane & 3;
    int wm = (w >> 2) * 64, wn = (w & 3) * 64;

    #pragma unroll
    for (int mi = 0; mi < 4; mi++) {
        int row = m0 + wm + 16 * mi + g;
        #pragma unroll
        for (int ni = 0; ni < 8; ni++) {
            int col = n0 + wn + 8 * ni + 2 * t;
            *(float2*)(out + (size_t)row * H_ + col) =
                make_float2(acc[mi][ni][0], acc[mi][ni][1]);
            *(float2*)(out + (size_t)(row + 8) * H_ + col) =
                make_float2(acc[mi][ni][2], acc[mi][ni][3]);
        }
    }
}

// ---------------------------------------------------------------------------
extern "C" void kernel_launch(void* const* d_in, const int* in_sizes, int n_in,
                              void* d_out, int out_size)
{
    const float* hs   = (const float*)d_in[0];
    const float* mask = (const float*)d_in[1];
    const int*   rel  = (const int*)  d_in[2];
    const float* Wq   = (const float*)d_in[3];
    const float* bq   = (const float*)d_in[4];
    const float* Wk   = (const float*)d_in[5];
    const float* bk   = (const float*)d_in[6];
    const float* Wv   = (const float*)d_in[7];
    const float* bv   = (const float*)d_in[8];
    const float* dist = (const float*)d_in[9];

    static bool attr_done = false;
    if (!attr_done) {
        cudaFuncSetAttribute(qkv_gemm,    cudaFuncAttributeMaxDynamicSharedMemorySize, SMEM_TN);
        cudaFuncSetAttribute(scores_gemm, cudaFuncAttributeMaxDynamicSharedMemorySize, SMEM_TN);
        cudaFuncSetAttribute(ctx_gemm,    cudaFuncAttributeMaxDynamicSharedMemorySize, SMEM_NN);
        attr_done = true;
    }

    __half* hs_r = nullptr;
    cudaGetSymbolAddress((void**)&hs_r, g_HS);

    dim3 blk(256);
    round_f16_kernel<<<(size_t)M_ * H_ / 2048, blk>>>(hs, hs_r);
    round_w_kernel<<<dim3(H_ * H_ / 2048, 1, 3), blk>>>(Wq, Wk, Wv);

    qkv_gemm<<<dim3(H_ / 256, M_ / 128, 3), blk, SMEM_TN>>>(bq, bk, bv);
    d1_kernel<<<M_ / 8, blk>>>(dist);
    scores_gemm<<<dim3(S_ / 256, S_ / 128, B_), blk, SMEM_TN>>>(rel, mask);
    softmax_k<<<M_, blk>>>();
    ctx_gemm<<<dim3(H_ / 256, S_ / 128, B_), blk, SMEM_NN>>>((float*)d_out);
}

// round 17
// speedup vs baseline: 1.1870x; 1.1870x over previous
#include <cuda_runtime.h>
#include <cuda_fp16.h>
#include <cstdint>

#define B_ 8
#define S_ 2048
#define H_ 1024
#define M_ (B_ * S_)   // 16384

// Scratch (static __device__ — allocation-free per harness rules)
static __device__ __half g_Q [(size_t)B_ * S_ * H_];   // 32 MB fp16
static __device__ __half g_K [(size_t)B_ * S_ * H_];   // 32 MB fp16
static __device__ __half g_V [(size_t)B_ * S_ * H_];   // 32 MB fp16
static __device__ __half g_Ph[(size_t)B_ * S_ * S_];   // 64 MB logits -> probs fp16
static __device__ float  g_d1[(size_t)B_ * S_];
static __device__ __half g_HS[(size_t)B_ * S_ * H_];   // 32 MB fp16 hidden_states
static __device__ __half g_W [(size_t)3 * H_ * H_];    // 6 MB fp16 Wq|Wk|Wv

// ---------------------------------------------------------------------------
// helpers
// ---------------------------------------------------------------------------
__device__ __forceinline__ void mma_f16(float c[4], const uint32_t a[4], const uint32_t b[2]) {
    asm volatile(
        "mma.sync.aligned.m16n8k16.row.col.f32.f16.f16.f32 "
        "{%0,%1,%2,%3}, {%4,%5,%6,%7}, {%8,%9}, {%0,%1,%2,%3};"
        : "+f"(c[0]), "+f"(c[1]), "+f"(c[2]), "+f"(c[3])
        : "r"(a[0]), "r"(a[1]), "r"(a[2]), "r"(a[3]), "r"(b[0]), "r"(b[1]));
}
__device__ __forceinline__ void ldsm_x4(uint32_t r[4], uint32_t addr) {
    asm volatile("ldmatrix.sync.aligned.m8n8.x4.shared.b16 {%0,%1,%2,%3}, [%4];"
        : "=r"(r[0]), "=r"(r[1]), "=r"(r[2]), "=r"(r[3]) : "r"(addr));
}
__device__ __forceinline__ void ldsm_x4_t(uint32_t r[4], uint32_t addr) {
    asm volatile("ldmatrix.sync.aligned.m8n8.x4.trans.shared.b16 {%0,%1,%2,%3}, [%4];"
        : "=r"(r[0]), "=r"(r[1]), "=r"(r[2]), "=r"(r[3]) : "r"(addr));
}
__device__ __forceinline__ void cp_async16(uint32_t smem_dst, const void* gsrc) {
    asm volatile("cp.async.cg.shared.global [%0], [%1], 16;\n" :: "r"(smem_dst), "l"(gsrc));
}
__device__ __forceinline__ void cp_commit() {
    asm volatile("cp.async.commit_group;\n" ::: "memory");
}
__device__ __forceinline__ void cp_wait1() {
    asm volatile("cp.async.wait_group 1;\n" ::: "memory");
}
__device__ __forceinline__ void cp_wait0() {
    asm volatile("cp.async.wait_group 0;\n" ::: "memory");
}
__device__ __forceinline__ uint32_t pack_h2(float a, float b) {
    __half2 h = __float22half2_rn(make_float2(a, b));
    return *(uint32_t*)&h;
}

// ---------------------------------------------------------------------------
// fp32 -> fp16 pre-round kernels
// ---------------------------------------------------------------------------
__global__ __launch_bounds__(256) void round_f16_kernel(
    const float* __restrict__ src, __half* __restrict__ dst)
{
    size_t i = ((size_t)blockIdx.x * 256 + threadIdx.x) * 8;
    float4 a = *(const float4*)(src + i);
    float4 b = *(const float4*)(src + i + 4);
    uint4 u;
    u.x = pack_h2(a.x, a.y); u.y = pack_h2(a.z, a.w);
    u.z = pack_h2(b.x, b.y); u.w = pack_h2(b.z, b.w);
    *(uint4*)(dst + i) = u;
}
__global__ __launch_bounds__(256) void round_w_kernel(
    const float* __restrict__ Wq, const float* __restrict__ Wk,
    const float* __restrict__ Wv)
{
    const float* src = (blockIdx.z == 0) ? Wq : (blockIdx.z == 1) ? Wk : Wv;
    __half* dst = g_W + (size_t)blockIdx.z * H_ * H_;
    size_t i = ((size_t)blockIdx.x * 256 + threadIdx.x) * 8;
    float4 a = *(const float4*)(src + i);
    float4 b = *(const float4*)(src + i + 4);
    uint4 u;
    u.x = pack_h2(a.x, a.y); u.y = pack_h2(a.z, a.w);
    u.z = pack_h2(b.x, b.y); u.w = pack_h2(b.z, b.w);
    *(uint4*)(dst + i) = u;
}

// ---------------------------------------------------------------------------
// Pipelined fp16 GEMM mainloop (R14-proven geometry):
// CTA tile 128x128, warp tile 64x32, KC=64, 2-stage cp.async, 2 CTAs/SM.
//   BMODE 0: Bsrc [N,K] row-major, staged Bs[n][k] pitch 72
//   BMODE 1: Bsrc [K,N] row-major, staged Bs[k][n] pitch 136, ldmatrix.trans
// 256 threads = 8 warps (2x4).
// ---------------------------------------------------------------------------
#define APITCH 72
#define ASZ (128 * APITCH)            // halves per A stage buffer
#define BSZ0 (128 * 72)
#define BSZ1 (64 * 136)

template<int BMODE>
__device__ __forceinline__ void gemm_pipe(
    const __half* __restrict__ A, int lda,
    const __half* __restrict__ Bsrc, int ldb,
    int m0, int n0, int K,
    __half* As, __half* Bs,
    float acc[4][4][4])
{
    const int BSZ = (BMODE == 0) ? BSZ0 : BSZ1;
    const uint32_t As_s = (uint32_t)__cvta_generic_to_shared(As);
    const uint32_t Bs_s = (uint32_t)__cvta_generic_to_shared(Bs);

    const int tid  = threadIdx.x;
    const int lane = tid & 31;
    const int w    = tid >> 5;
    const int wm   = (w >> 2) * 64;
    const int wn   = (w & 3)  * 32;

    // ldmatrix lane coords
    const int lrow = lane & 15;            // row within 16
    const int lc8  = (lane >> 4) * 8;      // 8-half column chunk
    const int tkoff = ((lane >> 3) & 1) * 8 + (lane & 7);  // trans: k row
    const int tnoff = (lane >> 4) * 8;                     // trans: n col

    // staging coords
    const int ar = tid >> 3, ac = (tid & 7) * 8;     // A/B0: 8 chunks/row
    const int br1 = tid >> 4, bc1 = (tid & 15) * 8;  // B1: 16 chunks/row

    auto stage = [&](int buf, int k0) {
        #pragma unroll
        for (int p = 0; p < 4; p++) {
            int r = ar + p * 32;
            cp_async16(As_s + (uint32_t)(buf * ASZ + r * APITCH + ac) * 2,
                       A + (size_t)(m0 + r) * lda + k0 + ac);
        }
        if (BMODE == 0) {
            #pragma unroll
            for (int p = 0; p < 4; p++) {
                int r = ar + p * 32;
                cp_async16(Bs_s + (uint32_t)(buf * BSZ0 + r * 72 + ac) * 2,
                           Bsrc + (size_t)(n0 + r) * ldb + k0 + ac);
            }
        } else {
            #pragma unroll
            for (int p = 0; p < 4; p++) {
                int r = br1 + p * 16;
                cp_async16(Bs_s + (uint32_t)(buf * BSZ1 + r * 136 + bc1) * 2,
                           Bsrc + (size_t)(k0 + r) * ldb + n0 + bc1);
            }
        }
        cp_commit();
    };

    stage(0, 0);
    int buf = 0;
    for (int k0 = 0; k0 < K; k0 += 64) {
        if (k0 + 64 < K) { stage(buf ^ 1, k0 + 64); cp_wait1(); }
        else             { cp_wait0(); }
        __syncthreads();

        const uint32_t Ab = As_s + (uint32_t)(buf * ASZ) * 2;
        const uint32_t Bb = Bs_s + (uint32_t)(buf * BSZ) * 2;

        #pragma unroll
        for (int ks = 0; ks < 4; ks++) {             // 4 x k16
            uint32_t af[4][4], bf[4][2];
            #pragma unroll
            for (int mi = 0; mi < 4; mi++)
                ldsm_x4(af[mi], Ab + (uint32_t)((wm + 16 * mi + lrow) * APITCH
                                                + ks * 16 + lc8) * 2);
            if (BMODE == 0) {
                #pragma unroll
                for (int p = 0; p < 2; p++) {
                    uint32_t t4[4];
                    ldsm_x4(t4, Bb + (uint32_t)((wn + 16 * p + lrow) * 72
                                                + ks * 16 + lc8) * 2);
                    bf[2 * p][0]     = t4[0];
                    bf[2 * p + 1][0] = t4[1];
                    bf[2 * p][1]     = t4[2];
                    bf[2 * p + 1][1] = t4[3];
                }
            } else {
                #pragma unroll
                for (int p = 0; p < 2; p++) {
                    uint32_t t4[4];
                    ldsm_x4_t(t4, Bb + (uint32_t)((ks * 16 + tkoff) * 136
                                                  + wn + 16 * p + tnoff) * 2);
                    bf[2 * p][0]     = t4[0];
                    bf[2 * p][1]     = t4[1];
                    bf[2 * p + 1][0] = t4[2];
                    bf[2 * p + 1][1] = t4[3];
                }
            }
            #pragma unroll
            for (int mi = 0; mi < 4; mi++)
                #pragma unroll
                for (int ni = 0; ni < 4; ni++)
                    mma_f16(acc[mi][ni], af[mi], bf[ni]);
        }
        __syncthreads();
        buf ^= 1;
    }
}

// Shared-memory footprints (bytes)
#define SMEM_TN  ((2 * ASZ + 2 * BSZ0) * 2)   // 73728 B (qkv, scores)
#define SMEM_NN  ((2 * ASZ + 2 * BSZ1) * 2)   // 71680 B (ctx)

// ---------------------------------------------------------------------------
// Kernel 1: QKV projections.  C[M,N] = HS[M,K] @ W[N,K]^T + bias -> fp16
// grid = (H/128, M/128, 3)
// ---------------------------------------------------------------------------
__global__ __launch_bounds__(256, 2) void qkv_gemm(
    const float* __restrict__ bq, const float* __restrict__ bk,
    const float* __restrict__ bv)
{
    extern __shared__ __align__(16) __half smem[];
    __half* As = smem;
    __half* Bs = smem + 2 * ASZ;

    int z = blockIdx.z;
    const __half* W = g_W + (size_t)z * H_ * H_;
    const float* bias = (z == 0) ? bq : (z == 1) ? bk : bv;
    __half* out = (z == 0) ? g_Q : (z == 1) ? g_K : g_V;

    int m0 = blockIdx.y * 128, n0 = blockIdx.x * 128;
    float acc[4][4][4] = {};

    gemm_pipe<0>(g_HS, H_, W, H_, m0, n0, H_, As, Bs, acc);

    int lane = threadIdx.x & 31, w = threadIdx.x >> 5;
    int g = lane >> 2, t = lane & 3;
    int wm = (w >> 2) * 64, wn = (w & 3) * 32;

    #pragma unroll
    for (int mi = 0; mi < 4; mi++) {
        int row = m0 + wm + 16 * mi + g;
        #pragma unroll
        for (int ni = 0; ni < 4; ni++) {
            int col = n0 + wn + 8 * ni + 2 * t;
            float b0 = bias[col], b1 = bias[col + 1];
            *(uint32_t*)(out + (size_t)row * H_ + col) =
                pack_h2(acc[mi][ni][0] + b0, acc[mi][ni][1] + b1);
            *(uint32_t*)(out + (size_t)(row + 8) * H_ + col) =
                pack_h2(acc[mi][ni][2] + b0, acc[mi][ni][3] + b1);
        }
    }
}

// ---------------------------------------------------------------------------
// Kernel 2: d1[b,q] = Q[b,q,:] . dist_emb[1,:]   (one warp per row)
// ---------------------------------------------------------------------------
__global__ __launch_bounds__(256) void d1_kernel(const float* __restrict__ dist)
{
    int row  = blockIdx.x * 8 + (threadIdx.x >> 5);
    int lane = threadIdx.x & 31;
    const __half2* q2 = (const __half2*)(g_Q + (size_t)row * H_);
    const float2*  e2 = (const float2*)(dist + H_);
    float s = 0.f;
    #pragma unroll 4
    for (int i = lane; i < H_ / 2; i += 32) {
        float2 q = __half22float2(q2[i]);
        float2 e = e2[i];
        s += q.x * e.x + q.y * e.y;
    }
    #pragma unroll
    for (int o = 16; o; o >>= 1) s += __shfl_xor_sync(0xffffffffu, s, o);
    if (lane == 0) g_d1[row] = s;
}

// ---------------------------------------------------------------------------
// Kernel 3: scores per batch -> fp16 logits in g_Ph.
// logit = (Q.K^T + d1*[rel==1]) / 32 + mask.  grid = (16, 16, B)
// ---------------------------------------------------------------------------
__global__ __launch_bounds__(256, 2) void scores_gemm(
    const int* __restrict__ rel, const float* __restrict__ mask)
{
    extern __shared__ __align__(16) __half smem[];
    __half* As = smem;
    __half* Bs = smem + 2 * ASZ;

    int b = blockIdx.z;
    const __half* A  = g_Q + (size_t)b * S_ * H_;
    const __half* Bt = g_K + (size_t)b * S_ * H_;
    __half* out        = g_Ph + (size_t)b * S_ * S_;
    const int* relb    = rel + (size_t)b * S_ * S_;
    const float* maskb = mask + (size_t)b * S_;

    int m0 = blockIdx.y * 128, n0 = blockIdx.x * 128;
    float acc[4][4][4] = {};

    gemm_pipe<0>(A, H_, Bt, H_, m0, n0, H_, As, Bs, acc);

    const float inv = 0.03125f;   // 1/sqrt(1024)
    int lane = threadIdx.x & 31, w = threadIdx.x >> 5;
    int g = lane >> 2, t = lane & 3;
    int wm = (w >> 2) * 64, wn = (w & 3) * 32;

    #pragma unroll
    for (int mi = 0; mi < 4; mi++) {
        int row = m0 + wm + 16 * mi + g;
        float dlo = g_d1[(size_t)b * S_ + row];
        float dhi = g_d1[(size_t)b * S_ + row + 8];
        #pragma unroll
        for (int ni = 0; ni < 4; ni++) {
            int col = n0 + wn + 8 * ni + 2 * t;
            float mk0 = maskb[col], mk1 = maskb[col + 1];
            int2 rlo = *(const int2*)(relb + (size_t)row * S_ + col);
            int2 rhi = *(const int2*)(relb + (size_t)(row + 8) * S_ + col);
            float o0 = (acc[mi][ni][0] + (rlo.x == 1 ? dlo : 0.f)) * inv + mk0;
            float o1 = (acc[mi][ni][1] + (rlo.y == 1 ? dlo : 0.f)) * inv + mk1;
            float o2 = (acc[mi][ni][2] + (rhi.x == 1 ? dhi : 0.f)) * inv + mk0;
            float o3 = (acc[mi][ni][3] + (rhi.y == 1 ? dhi : 0.f)) * inv + mk1;
            *(uint32_t*)(out + (size_t)row * S_ + col)       = pack_h2(o0, o1);
            *(uint32_t*)(out + (size_t)(row + 8) * S_ + col) = pack_h2(o2, o3);
        }
    }
}

// ---------------------------------------------------------------------------
// Kernel 4: row softmax over k (2048), in place fp16 on g_Ph.
// ---------------------------------------------------------------------------
__global__ __launch_bounds__(256) void softmax_k()
{
    __shared__ float red[32];
    int row = blockIdx.x;
    __half* p = g_Ph + (size_t)row * S_;
    int base = threadIdx.x * 8;

    uint4 u = *(const uint4*)(p + base);
    float x[8];
    {
        float2 a0 = __half22float2(*(__half2*)&u.x);
        float2 a1 = __half22float2(*(__half2*)&u.y);
        float2 a2 = __half22float2(*(__half2*)&u.z);
        float2 a3 = __half22float2(*(__half2*)&u.w);
        x[0]=a0.x; x[1]=a0.y; x[2]=a1.x; x[3]=a1.y;
        x[4]=a2.x; x[5]=a2.y; x[6]=a3.x; x[7]=a3.y;
    }

    float mx = x[0];
    #pragma unroll
    for (int i = 1; i < 8; i++) mx = fmaxf(mx, x[i]);
    #pragma unroll
    for (int o = 16; o; o >>= 1) mx = fmaxf(mx, __shfl_xor_sync(0xffffffffu, mx, o));
    int lane = threadIdx.x & 31, wid = threadIdx.x >> 5;
    if (lane == 0) red[wid] = mx;
    __syncthreads();
    if (wid == 0) {
        float m = (lane < 8) ? red[lane] : -1e30f;
        #pragma unroll
        for (int o = 4; o; o >>= 1) m = fmaxf(m, __shfl_xor_sync(0xffffffffu, m, o));
        if (lane == 0) red[0] = m;
    }
    __syncthreads();
    float m = red[0];

    float s = 0.f;
    #pragma unroll
    for (int i = 0; i < 8; i++) { x[i] = __expf(x[i] - m); s += x[i]; }
    #pragma unroll
    for (int o = 16; o; o >>= 1) s += __shfl_xor_sync(0xffffffffu, s, o);
    __syncthreads();
    if (lane == 0) red[wid] = s;
    __syncthreads();
    if (wid == 0) {
        float tt = (lane < 8) ? red[lane] : 0.f;
        #pragma unroll
        for (int o = 4; o; o >>= 1) tt += __shfl_xor_sync(0xffffffffu, tt, o);
        if (lane == 0) red[0] = tt;
    }
    __syncthreads();
    float invs = 1.0f / red[0];

    uint4 o;
    o.x = pack_h2(x[0] * invs, x[1] * invs);
    o.y = pack_h2(x[2] * invs, x[3] * invs);
    o.z = pack_h2(x[4] * invs, x[5] * invs);
    o.w = pack_h2(x[6] * invs, x[7] * invs);
    *(uint4*)(p + base) = o;
}

// ---------------------------------------------------------------------------
// Kernel 5: ctx per batch.  O = Ph @ V  (NN).  grid = (8, 16, B) -> fp32 d_out
// ---------------------------------------------------------------------------
__global__ __launch_bounds__(256, 2) void ctx_gemm(float* __restrict__ outp)
{
    extern __shared__ __align__(16) __half smem[];
    __half* As = smem;
    __half* Bs = smem + 2 * ASZ;

    int b = blockIdx.z;
    const __half* A  = g_Ph + (size_t)b * S_ * S_;
    const __half* Bm = g_V  + (size_t)b * S_ * H_;
    float* out = outp + (size_t)b * S_ * H_;

    int m0 = blockIdx.y * 128, n0 = blockIdx.x * 128;
    float acc[4][4][4] = {};

    gemm_pipe<1>(A, S_, Bm, H_, m0, n0, S_, As, Bs, acc);

    int lane = threadIdx.x & 31, w = threadIdx.x >> 5;
    int g = lane >> 2, t = lane & 3;
    int wm = (w >> 2) * 64, wn = (w & 3) * 32;

    #pragma unroll
    for (int mi = 0; mi < 4; mi++) {
        int row = m0 + wm + 16 * mi + g;
        #pragma unroll
        for (int ni = 0; ni < 4; ni++) {
            int col = n0 + wn + 8 * ni + 2 * t;
            *(float2*)(out + (size_t)row * H_ + col) =
                make_float2(acc[mi][ni][0], acc[mi][ni][1]);
            *(float2*)(out + (size_t)(row + 8) * H_ + col) =
                make_float2(acc[mi][ni][2], acc[mi][ni][3]);
        }
    }
}

// ---------------------------------------------------------------------------
extern "C" void kernel_launch(void* const* d_in, const int* in_sizes, int n_in,
                              void* d_out, int out_size)
{
    const float* hs   = (const float*)d_in[0];
    const float* mask = (const float*)d_in[1];
    const int*   rel  = (const int*)  d_in[2];
    const float* Wq   = (const float*)d_in[3];
    const float* bq   = (const float*)d_in[4];
    const float* Wk   = (const float*)d_in[5];
    const float* bk   = (const float*)d_in[6];
    const float* Wv   = (const float*)d_in[7];
    const float* bv   = (const float*)d_in[8];
    const float* dist = (const float*)d_in[9];

    static bool attr_done = false;
    if (!attr_done) {
        cudaFuncSetAttribute(qkv_gemm,    cudaFuncAttributeMaxDynamicSharedMemorySize, SMEM_TN);
        cudaFuncSetAttribute(scores_gemm, cudaFuncAttributeMaxDynamicSharedMemorySize, SMEM_TN);
        cudaFuncSetAttribute(ctx_gemm,    cudaFuncAttributeMaxDynamicSharedMemorySize, SMEM_NN);
        attr_done = true;
    }

    __half* hs_r = nullptr;
    cudaGetSymbolAddress((void**)&hs_r, g_HS);

    dim3 blk(256);
    round_f16_kernel<<<(size_t)M_ * H_ / 2048, blk>>>(hs, hs_r);
    round_w_kernel<<<dim3(H_ * H_ / 2048, 1, 3), blk>>>(Wq, Wk, Wv);

    qkv_gemm<<<dim3(H_ / 128, M_ / 128, 3), blk, SMEM_TN>>>(bq, bk, bv);
    d1_kernel<<<M_ / 8, blk>>>(dist);
    scores_gemm<<<dim3(S_ / 128, S_ / 128, B_), blk, SMEM_TN>>>(rel, mask);
    softmax_k<<<M_, blk>>>();
    ctx_gemm<<<dim3(H_ / 128, S_ / 128, B_), blk, SMEM_NN>>>((float*)d_out);
}